// round 8
// baseline (speedup 1.0000x reference)
#include <cuda_runtime.h>
#include <cuda_fp16.h>
#include <math.h>
#include <stdint.h>

#define BATCH   4
#define SEQLEN  4096
#define DIM     512
#define DINNER  1024
#define DSTATE  16
#define DCONV   4
#define M_TOK   (BATCH*SEQLEN)   // 16384

// ======================= PTX helpers (sm_80 baseline) ========================
__device__ __forceinline__ uint32_t smem_to_u32(const void* p) {
    uint32_t a;
    asm("{ .reg .u64 t; cvta.to.shared.u64 t, %1; cvt.u32.u64 %0, t; }"
        : "=r"(a) : "l"(p));
    return a;
}
#define CP_ASYNC16(saddr, gptr) \
    asm volatile("cp.async.cg.shared.global [%0], [%1], 16;" \
        :: "r"(saddr), "l"(gptr))
#define CP_COMMIT() asm volatile("cp.async.commit_group;" ::: "memory")
#define CP_WAIT1()  asm volatile("cp.async.wait_group 1;" ::: "memory")
#define CP_WAIT0()  asm volatile("cp.async.wait_group 0;" ::: "memory")

#define LDSM_X4(r, addr) \
    asm volatile("ldmatrix.sync.aligned.m8n8.x4.shared.b16 {%0,%1,%2,%3}, [%4];" \
        : "=r"((r)[0]), "=r"((r)[1]), "=r"((r)[2]), "=r"((r)[3]) : "r"(addr))

#define MMA_F16(d, a, b0, b1) \
    asm volatile("mma.sync.aligned.m16n8k16.row.col.f32.f16.f16.f32 " \
        "{%0,%1,%2,%3}, {%4,%5,%6,%7}, {%8,%9}, {%0,%1,%2,%3};" \
        : "+f"((d)[0]), "+f"((d)[1]), "+f"((d)[2]), "+f"((d)[3]) \
        : "r"((a)[0]), "r"((a)[1]), "r"((a)[2]), "r"((a)[3]), "r"(b0), "r"(b1))

// ======================= scratch =============================================
__device__ __align__(256) float g_xr  [(size_t)M_TOK * 2 * DINNER];
__device__ __align__(256) float g_xa  [(size_t)M_TOK * DINNER];
__device__ __align__(256) float g_wcat[2 * DSTATE * DINNER];
__device__ __align__(256) float g_dtb [(size_t)M_TOK * 2 * DSTATE];
__device__ __align__(256) float g_u   [M_TOK];
__device__ __align__(256) float g_adisc[(size_t)M_TOK * DSTATE];
__device__ __align__(256) float g_bu  [(size_t)M_TOK * DSTATE];
__device__ __align__(256) float g_y   [(size_t)M_TOK * DSTATE];
// fp16 GEMM operands
__device__ __align__(256) __half g_xh [(size_t)M_TOK * DIM];
__device__ __align__(256) __half g_yh [(size_t)M_TOK * DINNER];
__device__ __align__(256) __half g_wih[(size_t)2*DINNER * DIM];
__device__ __align__(256) __half g_woh[(size_t)DIM * DINNER];
// scan chunk summaries
#define SCHUNK  128
#define NCHUNK  (SEQLEN / SCHUNK)   // 32
__device__ float g_cA   [BATCH * DSTATE * NCHUNK];
__device__ float g_cV   [BATCH * DSTATE * NCHUNK];
__device__ float g_carry[BATCH * DSTATE * NCHUNK];

// ======================= HMMA fp16 GEMM ======================================
// C[M,N] = A[M,K] * B[N,K]^T, fp16 K-major inputs, fp32 out.
// Block tile 256x128, 256 threads (8 warps in 4x2, warp tile 64x64),
// K-chunk 64 halves (128B/row), cp.async double buffer, ldmatrix + mma.sync.
#define LG_ROWB   144
#define A_TILE_B  (256 * LG_ROWB)              // 36864 B
#define B_TILE_B  (128 * LG_ROWB)              // 18432 B
#define STAGE_B   (A_TILE_B + B_TILE_B)        // 55296 B
#define GH_SMEM   (2 * STAGE_B)                // 110592 B

__global__ __launch_bounds__(256, 1)
void gemm_hmma(const __half* __restrict__ A, const __half* __restrict__ B,
               float* __restrict__ C, int Nglob, int K)
{
    extern __shared__ char smem[];
    const uint32_t sb = smem_to_u32(smem);
    const int tid  = threadIdx.x;
    const int wid  = tid >> 5;
    const int lane = tid & 31;
    const int m0 = blockIdx.y * 256;
    const int n0 = blockIdx.x * 128;
    const int nch = K / 64;

    // warp -> 64(M) x 64(N) sub-tile; warps in 4x2 grid
    const int wm = (wid & 3) * 64;
    const int wn = (wid >> 2) * 64;

    float acc[4][8][4];
#pragma unroll
    for (int i = 0; i < 4; i++)
#pragma unroll
        for (int j = 0; j < 8; j++)
#pragma unroll
            for (int k = 0; k < 4; k++) acc[i][j][k] = 0.f;

    auto issue = [&](int c, int b) {
        const __half* Ag = A + (size_t)m0 * K + (size_t)c * 64;
        const __half* Bg = B + (size_t)n0 * K + (size_t)c * 64;
        const uint32_t sa  = sb + (uint32_t)(b * STAGE_B);
        const uint32_t sbm = sa + A_TILE_B;
        // A: 256 rows x 8 chunks of 16B = 2048 -> 8 per thread
#pragma unroll
        for (int i = 0; i < 8; i++) {
            int idx = tid + i * 256;
            int row = idx >> 3, cc = idx & 7;
            CP_ASYNC16(sa + (uint32_t)(row * LG_ROWB + cc * 16),
                       Ag + (size_t)row * K + cc * 8);
        }
        // B: 128 rows x 8 chunks = 1024 -> 4 per thread
#pragma unroll
        for (int i = 0; i < 4; i++) {
            int idx = tid + i * 256;
            int row = idx >> 3, cc = idx & 7;
            CP_ASYNC16(sbm + (uint32_t)(row * LG_ROWB + cc * 16),
                       Bg + (size_t)row * K + cc * 8);
        }
        CP_COMMIT();
    };

    issue(0, 0);
    for (int c = 0; c < nch; c++) {
        const int buf = c & 1;
        if (c + 1 < nch) { issue(c + 1, buf ^ 1); CP_WAIT1(); }
        else             { CP_WAIT0(); }
        __syncthreads();

        const uint32_t aBase = sb + (uint32_t)(buf * STAGE_B);
        const uint32_t bBase = aBase + A_TILE_B;
        const int lrow = lane & 15;
        const int lcol = (lane >> 4) * 16;
#pragma unroll
        for (int ks = 0; ks < 4; ks++) {
            uint32_t af[4][4], bfr[4][4];
#pragma unroll
            for (int mt = 0; mt < 4; mt++)
                LDSM_X4(af[mt], aBase + (uint32_t)((wm + mt*16 + lrow) * LG_ROWB + ks*32 + lcol));
#pragma unroll
            for (int ng = 0; ng < 4; ng++)
                LDSM_X4(bfr[ng], bBase + (uint32_t)((wn + ng*16 + lrow) * LG_ROWB + ks*32 + lcol));
#pragma unroll
            for (int mt = 0; mt < 4; mt++)
#pragma unroll
                for (int nt = 0; nt < 8; nt++) {
                    const int ng = nt >> 1, hi = nt & 1;
                    MMA_F16(acc[mt][nt], af[mt], bfr[ng][hi], bfr[ng][2 + hi]);
                }
        }
        __syncthreads();
    }

    const int er = lane >> 2;
    const int ec = (lane & 3) * 2;
#pragma unroll
    for (int mt = 0; mt < 4; mt++) {
        const int rbase = m0 + wm + mt * 16;
#pragma unroll
        for (int nt = 0; nt < 8; nt++) {
            const int col = n0 + wn + nt * 8 + ec;
            *reinterpret_cast<float2*>(C + (size_t)(rbase + er)     * Nglob + col) =
                make_float2(acc[mt][nt][0], acc[mt][nt][1]);
            *reinterpret_cast<float2*>(C + (size_t)(rbase + er + 8) * Nglob + col) =
                make_float2(acc[mt][nt][2], acc[mt][nt][3]);
        }
    }
}

// ======================= fp32 -> fp16 conversion ==============================
__global__ void tohalf_kernel(const float* __restrict__ src, __half* __restrict__ dst)
{
    long i = ((long)blockIdx.x * blockDim.x + threadIdx.x) * 4;
    float4 v = *reinterpret_cast<const float4*>(src + i);
    *reinterpret_cast<__half2*>(dst + i)     = __floats2half2_rn(v.x, v.y);
    *reinterpret_cast<__half2*>(dst + i + 2) = __floats2half2_rn(v.z, v.w);
}

// ======================= SIMT NT GEMM (small dt/B_proj only) =================
template<int BM, int BN, int BK, int TM, int TN>
__global__ __launch_bounds__((BM/TM)*(BN/TN))
void gemm_nt(const float* __restrict__ A, const float* __restrict__ B,
             float* __restrict__ C, int M, int N, int K)
{
    constexpr int TX = BN / TN;
    constexpr int TY = BM / TM;
    constexpr int NT = TX * TY;
    __shared__ float As[BK][BM];
    __shared__ float Bs[BK][BN];
    const int tid = threadIdx.x;
    const int tx = tid % TX, ty = tid / TX;
    const int m0 = blockIdx.y * BM, n0 = blockIdx.x * BN;
    float acc[TM][TN];
#pragma unroll
    for (int i = 0; i < TM; i++)
#pragma unroll
        for (int j = 0; j < TN; j++) acc[i][j] = 0.f;
    for (int k0 = 0; k0 < K; k0 += BK) {
#pragma unroll
        for (int i = tid; i < BM*BK/4; i += NT) {
            int r = i / (BK/4), c4 = i % (BK/4);
            float4 v = *reinterpret_cast<const float4*>(&A[(size_t)(m0+r)*K + k0 + c4*4]);
            As[c4*4+0][r]=v.x; As[c4*4+1][r]=v.y; As[c4*4+2][r]=v.z; As[c4*4+3][r]=v.w;
        }
#pragma unroll
        for (int i = tid; i < BN*BK/4; i += NT) {
            int r = i / (BK/4), c4 = i % (BK/4);
            float4 v = *reinterpret_cast<const float4*>(&B[(size_t)(n0+r)*K + k0 + c4*4]);
            Bs[c4*4+0][r]=v.x; Bs[c4*4+1][r]=v.y; Bs[c4*4+2][r]=v.z; Bs[c4*4+3][r]=v.w;
        }
        __syncthreads();
#pragma unroll
        for (int k = 0; k < BK; k++) {
            float ar[TM], br[TN];
#pragma unroll
            for (int i = 0; i < TM; i++) ar[i] = As[k][ty*TM+i];
#pragma unroll
            for (int j = 0; j < TN; j++) br[j] = Bs[k][tx*TN+j];
#pragma unroll
            for (int i = 0; i < TM; i++)
#pragma unroll
                for (int j = 0; j < TN; j++) acc[i][j] = fmaf(ar[i], br[j], acc[i][j]);
        }
        __syncthreads();
    }
#pragma unroll
    for (int i = 0; i < TM; i++) {
        float* crow = &C[(size_t)(m0+ty*TM+i)*N + n0 + tx*TN];
#pragma unroll
        for (int j = 0; j < TN; j++) crow[j] = acc[i][j];
    }
}

// ======================= pointwise / aux kernels =============================
__global__ void wcat_kernel(const float* __restrict__ Wx, const float* __restrict__ Wdt)
{
    int idx = blockIdx.x * blockDim.x + threadIdx.x;
    int row = idx >> 10;
    g_wcat[idx] = (row < DSTATE) ? Wdt[idx] : Wx[idx];
}

__global__ void conv_silu_kernel(const float* __restrict__ cw, const float* __restrict__ cb)
{
    int idx = blockIdx.x * blockDim.x + threadIdx.x;
    int c4 = idx & (DINNER/4 - 1);
    int m  = idx >> 8;
    int c  = c4 * 4;
    int l  = m & (SEQLEN - 1);
    float w[4][4];
#pragma unroll
    for (int j = 0; j < 4; j++)
        *reinterpret_cast<float4*>(w[j]) =
            *reinterpret_cast<const float4*>(cw + (size_t)(c + j) * DCONV);
    float4 b = *reinterpret_cast<const float4*>(cb + c);
    float a0 = b.x, a1 = b.y, a2 = b.z, a3 = b.w;
#pragma unroll
    for (int t = 0; t < DCONV; t++) {
        int ls = l - (DCONV - 1) + t;
        if (ls >= 0) {
            float4 xv = *reinterpret_cast<const float4*>(
                g_xr + (size_t)(m - (DCONV - 1) + t) * (2 * DINNER) + c);
            a0 = fmaf(w[0][t], xv.x, a0);
            a1 = fmaf(w[1][t], xv.y, a1);
            a2 = fmaf(w[2][t], xv.z, a2);
            a3 = fmaf(w[3][t], xv.w, a3);
        }
    }
    float4 o;
    o.x = a0 / (1.f + expf(-a0));
    o.y = a1 / (1.f + expf(-a1));
    o.z = a2 / (1.f + expf(-a2));
    o.w = a3 / (1.f + expf(-a3));
    *reinterpret_cast<float4*>(g_xa + (size_t)m * DINNER + c) = o;
}

__global__ void u_kernel()
{
    int gw = (blockIdx.x * blockDim.x + threadIdx.x) >> 5;
    int lane = threadIdx.x & 31;
    if (gw >= M_TOK) return;
    const float* xa = g_xa + (size_t)gw * DINNER;
    float v = xa[lane] + xa[lane + 32];
#pragma unroll
    for (int o = 16; o; o >>= 1) v += __shfl_down_sync(0xffffffffu, v, o);
    if (lane == 0) g_u[gw] = v * (1.f / 64.f);
}

__global__ void dtbu_kernel(const float* __restrict__ bdt, const float* __restrict__ Alog)
{
    int idx = blockIdx.x * blockDim.x + threadIdx.x;
    int m = idx >> 4;
    int n = idx & (DSTATE - 1);
    float raw = g_dtb[(size_t)m * 2 * DSTATE + n] + bdt[n];
    float dt  = raw > 20.f ? raw : log1pf(expf(raw));
    float bp  = g_dtb[(size_t)m * 2 * DSTATE + DSTATE + n];
    float A   = -expf(Alog[n]);
    g_adisc[idx] = expf(A * dt);
    g_bu[idx]    = dt * bp * g_u[m];
}

// -------- chunked scan (3 passes) --------
__global__ void scan_part_kernel()
{
    int t = blockIdx.x * blockDim.x + threadIdx.x;
    int chain = t >> 5, c = t & 31;
    int b = chain >> 4, n = chain & 15;
    size_t base = ((size_t)(b * SEQLEN + c * SCHUNK)) * DSTATE + n;
    float A = 1.f, V = 0.f;
#pragma unroll 8
    for (int i = 0; i < SCHUNK; i++) {
        float a = g_adisc[base + (size_t)i * DSTATE];
        float v = g_bu   [base + (size_t)i * DSTATE];
        V = fmaf(a, V, v);
        A *= a;
    }
    g_cA[chain * NCHUNK + c] = A;
    g_cV[chain * NCHUNK + c] = V;
}
__global__ void scan_mid_kernel()
{
    int chain = threadIdx.x;
    float s = 0.f;
#pragma unroll
    for (int c = 0; c < NCHUNK; c++) {
        g_carry[chain * NCHUNK + c] = s;
        s = fmaf(g_cA[chain * NCHUNK + c], s, g_cV[chain * NCHUNK + c]);
    }
}
__global__ void scan_apply_kernel()
{
    int t = blockIdx.x * blockDim.x + threadIdx.x;
    int chain = t >> 5, c = t & 31;
    int b = chain >> 4, n = chain & 15;
    size_t base = ((size_t)(b * SEQLEN + c * SCHUNK)) * DSTATE + n;
    float s = g_carry[chain * NCHUNK + c];
#pragma unroll 8
    for (int i = 0; i < SCHUNK; i++) {
        float a = g_adisc[base + (size_t)i * DSTATE];
        float v = g_bu   [base + (size_t)i * DSTATE];
        s = fmaf(a, s, v);
        g_y[base + (size_t)i * DSTATE] = s;
    }
}

// -------- gate + skip, fp16 output for GEMM2 ---------------------------------
__global__ void elt_kernel(const float* __restrict__ Dp)
{
    int idx = blockIdx.x * blockDim.x + threadIdx.x;
    int c4 = idx & (DINNER/4 - 1);
    int m  = idx >> 8;
    int c  = c4 * 4;
    float yv  = g_y[(size_t)m * DSTATE + (c >> 6)];
    float4 xa = *reinterpret_cast<const float4*>(g_xa + (size_t)m * DINNER + c);
    float4 D  = *reinterpret_cast<const float4*>(Dp + c);
    float4 r  = *reinterpret_cast<const float4*>(g_xr + (size_t)m * 2 * DINNER + DINNER + c);
    float4 o;
    o.x = (yv + xa.x * D.x) * (r.x / (1.f + expf(-r.x)));
    o.y = (yv + xa.y * D.y) * (r.y / (1.f + expf(-r.y)));
    o.z = (yv + xa.z * D.z) * (r.z / (1.f + expf(-r.z)));
    o.w = (yv + xa.w * D.w) * (r.w / (1.f + expf(-r.w)));

    __half* row = g_yh + (size_t)m * DINNER;
    *reinterpret_cast<__half2*>(row + c)     = __floats2half2_rn(o.x, o.y);
    *reinterpret_cast<__half2*>(row + c + 2) = __floats2half2_rn(o.z, o.w);
}

// ======================= launch ==============================================
extern "C" void kernel_launch(void* const* d_in, const int* in_sizes, int n_in,
                              void* d_out, int out_size)
{
    const float* x      = (const float*)d_in[0];
    const float* W_in   = (const float*)d_in[1];
    const float* conv_w = (const float*)d_in[2];
    const float* conv_b = (const float*)d_in[3];
    const float* W_x    = (const float*)d_in[4];
    const float* W_dt   = (const float*)d_in[5];
    const float* b_dt   = (const float*)d_in[6];
    const float* A_log  = (const float*)d_in[7];
    const float* D_par  = (const float*)d_in[8];
    const float* W_out  = (const float*)d_in[9];
    float* out = (float*)d_out;

    float* xr;   cudaGetSymbolAddress((void**)&xr,   g_xr);
    float* xa;   cudaGetSymbolAddress((void**)&xa,   g_xa);
    float* wcat; cudaGetSymbolAddress((void**)&wcat, g_wcat);
    float* dtb;  cudaGetSymbolAddress((void**)&dtb,  g_dtb);
    __half* xh;  cudaGetSymbolAddress((void**)&xh,  g_xh);
    __half* yh;  cudaGetSymbolAddress((void**)&yh,  g_yh);
    __half* wih; cudaGetSymbolAddress((void**)&wih, g_wih);
    __half* woh; cudaGetSymbolAddress((void**)&woh, g_woh);

    cudaFuncSetAttribute(gemm_hmma, cudaFuncAttributeMaxDynamicSharedMemorySize, GH_SMEM);

    // weight / input conversion to fp16
    wcat_kernel<<<(2*DSTATE*DINNER)/256, 256>>>(W_x, W_dt);
    tohalf_kernel<<<(2*DINNER*DIM)/1024, 256>>>(W_in, wih);
    tohalf_kernel<<<(DIM*DINNER)/1024, 256>>>(W_out, woh);
    tohalf_kernel<<<((long)M_TOK*DIM)/1024, 256>>>(x, xh);

    // GEMM1: xr = x @ W_in^T   [16384 x 2048 x 512] fp16 HMMA
    gemm_hmma<<<dim3(2*DINNER/128, M_TOK/256), 256, GH_SMEM>>>(
        xh, wih, xr, 2*DINNER, DIM);

    conv_silu_kernel<<<(M_TOK*(DINNER/4))/256, 256>>>(conv_w, conv_b);
    u_kernel<<<(M_TOK*32)/256, 256>>>();

    // small GEMM: [16384 x 32 x 1024] fp32 SIMT
    gemm_nt<64,32,16,4,2><<<dim3(1, M_TOK/64), 256>>>(xa, wcat, dtb, M_TOK, 2*DSTATE, DINNER);

    dtbu_kernel<<<(M_TOK*DSTATE)/256, 256>>>(b_dt, A_log);

    scan_part_kernel<<<(BATCH*DSTATE*NCHUNK)/256, 256>>>();
    scan_mid_kernel<<<1, BATCH*DSTATE>>>();
    scan_apply_kernel<<<(BATCH*DSTATE*NCHUNK)/256, 256>>>();

    elt_kernel<<<(M_TOK*(DINNER/4))/256, 256>>>(D_par);

    // GEMM2: out = y_full @ W_out^T  [16384 x 512 x 1024] fp16 HMMA
    gemm_hmma<<<dim3(DIM/128, M_TOK/256), 256, GH_SMEM>>>(
        yh, woh, out, DIM, DINNER);
}